// round 8
// baseline (speedup 1.0000x reference)
#include <cuda_runtime.h>

// L1Distance, dual-path pipe-balanced formulation.
// Per accumulator (compile-time choice):
//   direct path (1/3 of accs):  acc += |a - b|          (2 FADD, fma pipe)
//   min path    (2/3 of accs):  acc += min(a, b)        (FMNMX alu + FADD fma)
//      -> out = rsA + rsB - 2*acc  (mean adjustment cancels exactly)
// Pipe cost per pair: fma = 1 - 0.5p, alu = p (SM-cycles); p = 2/3 balances
// both pipes at 2/3 of the single-pipe wall measured in R1/R3-R7.

constexpr int D   = 64;
constexpr int TM  = 128;   // tile rows (x1)
constexpr int TN  = 64;    // tile cols (x2)
constexpr int DC  = 32;    // d staged in two chunks
constexpr int SAA = 132;   // As stride (128 + 4 pad)
constexpr int SAB = 68;    // Bs stride (64 + 4 pad)

// path selector: true -> direct |a-b|, false -> min-identity
__device__ __host__ constexpr bool is_direct(int m, int n) {
    return ((m * 4 + n) % 3) == 0;   // 11 of 32 accs ~ 1/3
}

__global__ __launch_bounds__(256, 3)
void l1dist_kernel(const float* __restrict__ x1, const float* __restrict__ x2,
                   float* __restrict__ out, int N2) {
    __shared__ __align__(16) float As[DC * SAA];  // As[d][row] = x1[i0+row][dc+d]
    __shared__ __align__(16) float Bs[DC * SAB];  // Bs[d][row] = x2[j0+row][dc+d]
    __shared__ float rsAs[TM];
    __shared__ float rsBs[TN];

    const int i0  = blockIdx.y * TM;
    const int j0  = blockIdx.x * TN;
    const int tid = (int)threadIdx.x;
    const int ty  = tid >> 4;   // 0..15 -> 8 rows each
    const int tx  = tid & 15;   // 0..15 -> 4 cols each

    float acc[8][4];
#pragma unroll
    for (int m = 0; m < 8; m++)
#pragma unroll
        for (int n = 0; n < 4; n++) acc[m][n] = 0.0f;

    float rs = 0.0f;   // per-thread rowsum piece (threads 0..191)

    for (int dc = 0; dc < D; dc += DC) {
        // ---- stage A: 128 rows x 32 d = 1024 float4, 4 per thread ----
#pragma unroll
        for (int k = 0; k < 4; k++) {
            int idx = tid + k * 256;
            int row = idx >> 3;             // 0..127
            int d4  = (idx & 7) << 2;       // 0,4,...,28
            float4 a = *(const float4*)(x1 + (size_t)(i0 + row) * D + dc + d4);
            As[(d4 + 0) * SAA + row] = a.x;
            As[(d4 + 1) * SAA + row] = a.y;
            As[(d4 + 2) * SAA + row] = a.z;
            As[(d4 + 3) * SAA + row] = a.w;
        }
        // ---- stage B: 64 rows x 32 d = 512 float4, 2 per thread ----
#pragma unroll
        for (int k = 0; k < 2; k++) {
            int idx = tid + k * 256;
            int row = idx >> 3;             // 0..63
            int d4  = (idx & 7) << 2;
            float4 b = *(const float4*)(x2 + (size_t)(j0 + row) * D + dc + d4);
            Bs[(d4 + 0) * SAB + row] = b.x;
            Bs[(d4 + 1) * SAB + row] = b.y;
            Bs[(d4 + 2) * SAB + row] = b.z;
            Bs[(d4 + 3) * SAB + row] = b.w;
        }
        __syncthreads();

        // ---- partial rowsums from staged tiles (warps 0..5) ----
        if (tid < TM) {
            const float* col = &As[tid];
#pragma unroll
            for (int d = 0; d < DC; d++) rs += col[d * SAA];
        } else if (tid < TM + TN) {
            const float* col = &Bs[tid - TM];
#pragma unroll
            for (int d = 0; d < DC; d++) rs += col[d * SAB];
        }

        // ---- compute: mixed-path inner loop ----
#pragma unroll 8
        for (int d = 0; d < DC; d++) {
            float4 a0 = *(const float4*)(&As[d * SAA] + ty * 8);
            float4 a1 = *(const float4*)(&As[d * SAA] + ty * 8 + 4);
            float4 bv = *(const float4*)(&Bs[d * SAB] + tx * 4);
            float ra[8] = {a0.x, a0.y, a0.z, a0.w, a1.x, a1.y, a1.z, a1.w};
            float rb[4] = {bv.x, bv.y, bv.z, bv.w};
#pragma unroll
            for (int m = 0; m < 8; m++)
#pragma unroll
                for (int n = 0; n < 4; n++) {
                    if (is_direct(m, n))
                        acc[m][n] += fabsf(ra[m] - rb[n]);   // 2x FADD (fma)
                    else
                        acc[m][n] += fminf(ra[m], rb[n]);    // FMNMX (alu) + FADD (fma)
                }
        }
        __syncthreads();
    }

    // ---- publish rowsums, then epilogue ----
    if (tid < TM)            rsAs[tid] = rs;
    else if (tid < TM + TN)  rsBs[tid - TM] = rs;
    __syncthreads();

    float rsb[4] = {rsBs[tx * 4 + 0], rsBs[tx * 4 + 1],
                    rsBs[tx * 4 + 2], rsBs[tx * 4 + 3]};
#pragma unroll
    for (int m = 0; m < 8; m++) {
        float rsa = rsAs[ty * 8 + m];
        int r = i0 + ty * 8 + m;
        float* orow = out + (size_t)r * N2 + j0 + tx * 4;
        float v[4];
#pragma unroll
        for (int n = 0; n < 4; n++) {
            if (is_direct(m, n))
                v[n] = fmaxf(acc[m][n], 0.f);
            else
                v[n] = fmaxf(fmaf(-2.f, acc[m][n], rsa + rsb[n]), 0.f);
        }
        *(float4*)orow = make_float4(v[0], v[1], v[2], v[3]);
    }
}

extern "C" void kernel_launch(void* const* d_in, const int* in_sizes, int n_in,
                              void* d_out, int out_size) {
    const float* x1 = (const float*)d_in[0];
    const float* x2 = (const float*)d_in[1];
    float* out = (float*)d_out;

    int N1 = in_sizes[0] / D;   // 2048
    int N2 = in_sizes[1] / D;   // 2048

    dim3 grid(N2 / TN, N1 / TM);   // 32 x 16 = 512 blocks
    l1dist_kernel<<<grid, 256>>>(x1, x2, out, N2);
}

// round 9
// speedup vs baseline: 1.0088x; 1.0088x over previous
#include <cuda_runtime.h>

// L1Distance via the min identity + packed f32x2 accumulation:
//   out[i][j] = max(rsA[i] + rsB[j] - 2 * sum_d min(x1[i,d], x2[j,d]), 0)
// Per 2 pairs: 2 FMNMX (alu) + 1 add.rn.f32x2 (fma); the mov.b64 pack is
// elided by ptxas register-pair allocation (verified in R7: issue% scaled
// exactly with the 1.5-slots/pair model). 64x64 tiles, whole D staged once,
// 4 CTAs/SM for 8 warps/SMSP, 1024-CTA grid to smooth the wave tail.

constexpr int D  = 64;
constexpr int TM = 64;
constexpr int TN = 64;
constexpr int SA = 68;   // padded stride (floats)

__device__ __forceinline__ void acc2(unsigned long long& acc, float lo, float hi) {
    unsigned long long t;
    asm("mov.b64 %0, {%1, %2};" : "=l"(t) : "f"(lo), "f"(hi));
    asm("add.rn.f32x2 %0, %0, %1;" : "+l"(acc) : "l"(t));
}

__global__ __launch_bounds__(256, 4)
void l1dist_kernel(const float* __restrict__ x1, const float* __restrict__ x2,
                   float* __restrict__ out, int N2) {
    __shared__ __align__(16) float As[D * SA];  // As[d][row] = x1[i0+row][d]
    __shared__ __align__(16) float Bs[D * SA];  // Bs[d][row] = x2[j0+row][d]
    __shared__ float rsAs[TM];
    __shared__ float rsBs[TN];

    const int i0  = blockIdx.y * TM;
    const int j0  = blockIdx.x * TN;
    const int tid = (int)threadIdx.x;
    const int ty  = tid >> 4;   // 0..15 -> rows ty*4..ty*4+3
    const int tx  = tid & 15;   // 0..15 -> cols tx*4..tx*4+3

    // ---- stage both tiles transposed: 64 rows x 64 d = 1024 float4 each ----
#pragma unroll
    for (int k = 0; k < 4; k++) {
        int idx = tid + k * 256;        // 0..1023
        int row = idx >> 4;             // 0..63
        int d4  = (idx & 15) << 2;      // 0,4,...,60
        float4 a = *(const float4*)(x1 + (size_t)(i0 + row) * D + d4);
        As[(d4 + 0) * SA + row] = a.x;
        As[(d4 + 1) * SA + row] = a.y;
        As[(d4 + 2) * SA + row] = a.z;
        As[(d4 + 3) * SA + row] = a.w;
        float4 b = *(const float4*)(x2 + (size_t)(j0 + row) * D + d4);
        Bs[(d4 + 0) * SA + row] = b.x;
        Bs[(d4 + 1) * SA + row] = b.y;
        Bs[(d4 + 2) * SA + row] = b.z;
        Bs[(d4 + 3) * SA + row] = b.w;
    }
    __syncthreads();

    // ---- in-block rowsums from staged tiles (threads 0..127) ----
    if (tid < TM + TN) {
        const float* col = (tid < TM) ? &As[tid] : &Bs[tid - TM];
        float s = 0.f;
#pragma unroll
        for (int d = 0; d < D; d++) s += col[d * SA];
        if (tid < TM) rsAs[tid] = s;
        else          rsBs[tid - TM] = s;
    }

    // ---- main compute: packed accumulation of mins ----
    // acc[m][p] holds packed sums for cols (tx*4+2p, tx*4+2p+1)
    unsigned long long acc[4][2];
#pragma unroll
    for (int m = 0; m < 4; m++) { acc[m][0] = 0ULL; acc[m][1] = 0ULL; }

#pragma unroll 16
    for (int d = 0; d < D; d++) {
        float4 av = *(const float4*)(&As[d * SA] + ty * 4);
        float4 bv = *(const float4*)(&Bs[d * SA] + tx * 4);
        float ra[4] = {av.x, av.y, av.z, av.w};
#pragma unroll
        for (int m = 0; m < 4; m++) {
            acc2(acc[m][0], fminf(ra[m], bv.x), fminf(ra[m], bv.y));
            acc2(acc[m][1], fminf(ra[m], bv.z), fminf(ra[m], bv.w));
        }
    }
    __syncthreads();   // rowsum writes -> epilogue reads

    // ---- epilogue: out = max(rsA + rsB - 2*accmin, 0) ----
    float rsb[4] = {rsBs[tx * 4 + 0], rsBs[tx * 4 + 1],
                    rsBs[tx * 4 + 2], rsBs[tx * 4 + 3]};
#pragma unroll
    for (int m = 0; m < 4; m++) {
        float rsa = rsAs[ty * 4 + m];
        int r = i0 + ty * 4 + m;
        float* orow = out + (size_t)r * N2 + j0 + tx * 4;
        float2 p0 = *(float2*)&acc[m][0];
        float2 p1 = *(float2*)&acc[m][1];
        float v0 = fmaxf(fmaf(-2.f, p0.x, rsa + rsb[0]), 0.f);
        float v1 = fmaxf(fmaf(-2.f, p0.y, rsa + rsb[1]), 0.f);
        float v2 = fmaxf(fmaf(-2.f, p1.x, rsa + rsb[2]), 0.f);
        float v3 = fmaxf(fmaf(-2.f, p1.y, rsa + rsb[3]), 0.f);
        *(float4*)orow = make_float4(v0, v1, v2, v3);
    }
}

extern "C" void kernel_launch(void* const* d_in, const int* in_sizes, int n_in,
                              void* d_out, int out_size) {
    const float* x1 = (const float*)d_in[0];
    const float* x2 = (const float*)d_in[1];
    float* out = (float*)d_out;

    int N1 = in_sizes[0] / D;   // 2048
    int N2 = in_sizes[1] / D;   // 2048

    dim3 grid(N2 / TN, N1 / TM);   // 32 x 32 = 1024 blocks
    l1dist_kernel<<<grid, 256>>>(x1, x2, out, N2);
}